// round 12
// baseline (speedup 1.0000x reference)
#include <cuda_runtime.h>
#include <cuda_bf16.h>
#include <cuda_fp16.h>
#include <math.h>
#include <stdint.h>

// Problem constants
#define BATCH   2
#define C1      64
#define IN_CH   128
#define OFF_CH  256
#define OUT_CH  64
#define H1      128
#define W1      128
#define H       256
#define W       256
#define HW      (H*W)
#define BN_EPS  1e-5f
#define BN_N    ((float)(BATCH*H*W))

// ---------------- scratch ------------------------------------------------------
__device__ float g_up  [(size_t)BATCH * C1 * HW];
__device__ float g_off [(size_t)BATCH * OFF_CH * HW];
__device__ float g_pre1[(size_t)BATCH * OUT_CH * HW];
__device__ float g_stats[4 * OUT_CH];
__device__ float g_bn   [4 * OUT_CH];

// NHWC fp16 planes ([b][pix][ic], ic contiguous)
__device__ __half g_xc16[(size_t)BATCH * HW * IN_CH];
__device__ __half g_xd16[(size_t)BATCH * HW * IN_CH];
__device__ __half g_p116[(size_t)BATCH * HW * OUT_CH];

// packed fp16 weights [tap][oc][ic]
__device__ __half g_w_off16[9 * OFF_CH * IN_CH];
__device__ __half g_w_c116 [9 * OUT_CH * IN_CH];
__device__ __half g_w_c216 [9 * OUT_CH * OUT_CH];

// ---------------- PTX helpers ----------------------------------------------------
__device__ __forceinline__ uint32_t smem_u32(const void* p) {
    uint32_t a;
    asm("{ .reg .u64 t; cvta.to.shared.u64 t, %1; cvt.u32.u64 %0, t; }"
        : "=r"(a) : "l"(p));
    return a;
}
__device__ __forceinline__ void ldmx4(uint32_t* r, uint32_t a) {
    asm volatile("ldmatrix.sync.aligned.m8n8.x4.shared.b16 {%0,%1,%2,%3}, [%4];"
        : "=r"(r[0]), "=r"(r[1]), "=r"(r[2]), "=r"(r[3]) : "r"(a));
}
__device__ __forceinline__ void ldmx2(uint32_t* r, uint32_t a) {
    asm volatile("ldmatrix.sync.aligned.m8n8.x2.shared.b16 {%0,%1}, [%2];"
        : "=r"(r[0]), "=r"(r[1]) : "r"(a));
}
__device__ __forceinline__ void mma_fp16(float* d, const uint32_t* A, const uint32_t* B) {
    asm volatile(
        "mma.sync.aligned.m16n8k16.row.col.f32.f16.f16.f32 "
        "{%0,%1,%2,%3}, {%4,%5,%6,%7}, {%8,%9}, {%0,%1,%2,%3};"
        : "+f"(d[0]), "+f"(d[1]), "+f"(d[2]), "+f"(d[3])
        : "r"(A[0]), "r"(A[1]), "r"(A[2]), "r"(A[3]), "r"(B[0]), "r"(B[1]));
}
__device__ __forceinline__ void cp_async16(uint32_t dst, const void* src, uint32_t srcsize) {
    asm volatile("cp.async.cg.shared.global [%0], [%1], 16, %2;"
                 :: "r"(dst), "l"(src), "r"(srcsize) : "memory");
}
#define CP_COMMIT() asm volatile("cp.async.commit_group;" ::: "memory")
#define CP_WAIT1()  asm volatile("cp.async.wait_group 1;" ::: "memory")
#define CP_WAIT0()  asm volatile("cp.async.wait_group 0;" ::: "memory")

// ---------------- small kernels ----------------------------------------------------
__global__ void init_stats_kernel() { g_stats[threadIdx.x] = 0.f; }

// (OC,IC,3,3) fp32 -> [tap][oc][ic] fp16
__global__ void pack_weights16_kernel(const float* __restrict__ w,
                                      __half* __restrict__ dst,
                                      int OC, int IC) {
    int idx = blockIdx.x * blockDim.x + threadIdx.x;
    int total = 9 * OC * IC;
    if (idx >= total) return;
    int ic  = idx % IC;
    int rem = idx / IC;
    int oc  = rem % OC;
    int tap = rem / OC;
    dst[idx] = __float2half_rn(w[((size_t)oc * IC + ic) * 9 + tap]);
}

// ConvTranspose2d(2,2,s=2): thread computes 2x2 output block of one o-channel
__global__ void upcat2_kernel(const float* __restrict__ x1,
                              const float* __restrict__ up_w,
                              const float* __restrict__ up_b) {
    __shared__ float w4[64][4];
    int tid = threadIdx.x;
    int o = blockIdx.y, b = blockIdx.z;
    {
        int i = tid >> 2, k = tid & 3;
        w4[i][k] = up_w[((size_t)i * 64 + o) * 4 + k];
    }
    __syncthreads();
    int pix = blockIdx.x * 256 + tid;
    int ys = pix >> 7, xs = pix & 127;
    float bv = up_b[o];
    float a0 = bv, a1 = bv, a2 = bv, a3 = bv;
    const float* xp = x1 + (size_t)b * C1 * H1 * W1 + pix;
    #pragma unroll 8
    for (int i = 0; i < 64; ++i) {
        float v = __ldg(xp + (size_t)i * (H1 * W1));
        a0 = fmaf(v, w4[i][0], a0);
        a1 = fmaf(v, w4[i][1], a1);
        a2 = fmaf(v, w4[i][2], a2);
        a3 = fmaf(v, w4[i][3], a3);
    }
    float* dst = g_up + ((size_t)(b * C1 + o) * H + 2 * ys) * W + 2 * xs;
    *(float2*)dst = make_float2(a0, a1);
    *(float2*)(dst + W) = make_float2(a2, a3);
}

// NCHW fp32 (two srcs, split at S) -> NHWC fp16 (optional BN+ReLU). block (32,8).
__global__ void nchw_to_fp16_kernel(const float* __restrict__ src_lo,
                                    const float* __restrict__ src_hi,
                                    __half* __restrict__ dst, int C, int S,
                                    const float* __restrict__ sc,
                                    const float* __restrict__ sh) {
    __shared__ float t[32][33];
    int tx = threadIdx.x, ty = threadIdx.y;
    int pix0 = blockIdx.x * 32, cg = blockIdx.y * 32, b = blockIdx.z;
    #pragma unroll
    for (int i = 0; i < 4; ++i) {
        int c = cg + ty + i * 8;
        const float* sp = (c < S) ? src_lo + ((size_t)b * S + c) * HW
                                  : src_hi + ((size_t)b * (C - S) + c - S) * HW;
        float v = sp[pix0 + tx];
        if (sc) v = fmaxf(fmaf(v, __ldg(sc + c), __ldg(sh + c)), 0.f);
        t[ty + i * 8][tx] = v;
    }
    __syncthreads();
    #pragma unroll
    for (int i = 0; i < 4; ++i) {
        int pxl = ty + i * 8;
        size_t o = ((size_t)b * HW + pix0 + pxl) * C + cg + tx;
        dst[o] = __float2half_rn(t[tx][pxl]);
    }
}

// deformable gather fused with NHWC fp16 transpose. block (32,8).
__global__ void gather_nhwc_kernel(const float* __restrict__ x2) {
    __shared__ float t[32][33];
    int tx = threadIdx.x, ty = threadIdx.y;
    int pix0 = blockIdx.x * 32, cg = blockIdx.y * 32, b = blockIdx.z;
    int pix = pix0 + tx;
    int x = pix & (W - 1), y = pix >> 8;
    const float* ob = g_off + (size_t)b * OFF_CH * HW;
    #pragma unroll
    for (int i = 0; i < 4; ++i) {
        int c = cg + ty + i * 8;
        size_t flat = 2 * ((size_t)c * HW + pix);
        float oy = ob[flat];
        float ox = ob[flat + 1];
        float cy = fminf(fmaxf(oy + (float)y, 0.f), (float)(H - 1));
        float cx = fminf(fmaxf(ox + (float)x, 0.f), (float)(W - 1));
        float y0f = floorf(cy), x0f = floorf(cx);
        int y0 = (int)y0f, y1 = (int)ceilf(cy);
        int xx0 = (int)x0f, xx1 = (int)ceilf(cx);
        const float* xp = (c < C1) ? x2 + ((size_t)b * C1 + c) * HW
                                   : g_up + ((size_t)b * C1 + c - C1) * HW;
        float v00 = xp[y0 * W + xx0];
        float v10 = xp[y1 * W + xx0];
        float v01 = xp[y0 * W + xx1];
        float v11 = xp[y1 * W + xx1];
        float wy = cy - y0f, wx = cx - x0f;
        float vt = fmaf(v10 - v00, wy, v00);
        float vb = fmaf(v11 - v01, wy, v01);
        t[ty + i * 8][tx] = fmaf(vb - vt, wx, vt);
    }
    __syncthreads();
    #pragma unroll
    for (int i = 0; i < 4; ++i) {
        int pxl = ty + i * 8;
        size_t o = ((size_t)b * HW + pix0 + pxl) * IN_CH + cg + tx;
        g_xd16[o] = __float2half_rn(t[tx][pxl]);
    }
}

// ---------------- fp16 HMMA conv, warp tile 64x64, A-row reuse --------------------
// Block: BM px x BN oc, 4 warps = (BM/64) m-warps x (BN/64) n-warps, warp 64x64.
// Stage = (icc, dy row): one (BM+2)-px A row + B for 3 dx taps; COMPUTE iterates dx
// by offsetting A base by one pixel (144B). MODE 0: plain. MODE 1: +bias,+stats.
template <int IC, int MODE, int BM, int BN>
__global__ __launch_bounds__(128, 1)
void conv_hmma_kernel(const __half* __restrict__ xin,
                      const __half* __restrict__ wgt,
                      int OC,
                      const float* __restrict__ bias, float* __restrict__ out,
                      float* __restrict__ st_sum, float* __restrict__ st_sq) {
    extern __shared__ __align__(128) char smem[];
    constexpr int NSTAGE = (IC / 64) * 3;
    constexpr int A_PX  = BM + 2;
    constexpr int A_SZ  = A_PX * 144;
    constexpr int B_TAP = BN * 144;
    constexpr int SBUF  = A_SZ + 3 * B_TAP;
    constexpr int WM    = BM / 64;               // warps along M
    constexpr int ACH   = A_PX * 8;              // 16B chunks in A row
    constexpr int BCH   = 3 * BN * 8;            // 16B chunks in B (3 taps)

    const int tid = threadIdx.x, lane = tid & 31, wid = tid >> 5;
    const int wm = wid % WM, wn = wid / WM;
    int y, x0;
    if (BM == 128) { y = blockIdx.x >> 1; x0 = (blockIdx.x & 1) * 128; }
    else           { y = blockIdx.x;      x0 = 0; }
    const int b  = blockIdx.z;
    const int oc0 = blockIdx.y * BN;
    const uint32_t sb = smem_u32(smem);
    const __half* xb = xin + (size_t)b * HW * IC;

    float acc[WM == 2 ? 4 : 4][8][4];
    #pragma unroll
    for (int mf = 0; mf < 4; ++mf)
        #pragma unroll
        for (int nf = 0; nf < 8; ++nf)
            #pragma unroll
            for (int q = 0; q < 4; ++q) acc[mf][nf][q] = 0.f;

#define FILL(S, BO) do {                                                            \
    const int _s = (S);                                                             \
    const int _icc = (IC == 128) ? (_s / 3) : 0;                                    \
    const int _r   = (IC == 128) ? (_s % 3) : _s;                                   \
    const int _ys = y + _r - 1;                                                     \
    const bool _yok = (_ys >= 0) && (_ys < H);                                      \
    _Pragma("unroll")                                                               \
    for (int _k = 0; _k < (ACH + 127) / 128; ++_k) {                                \
        int _c = tid + _k * 128;                                                    \
        if (_c < ACH) {                                                             \
            int _px = _c >> 3, _co = _c & 7;                                        \
            int _xs = x0 + _px - 1;                                                 \
            bool _ok = _yok && (_xs >= 0) && (_xs < W);                             \
            size_t _po = _ok ? ((size_t)_ys * W + _xs) * IC : 0;                    \
            cp_async16(sb + (BO) + _px * 144 + _co * 16,                            \
                       (const char*)(xb + _po) + _icc * 128 + _co * 16,             \
                       _ok ? 16u : 0u);                                             \
        }                                                                           \
    }                                                                               \
    _Pragma("unroll")                                                               \
    for (int _k = 0; _k < BCH / 128; ++_k) {                                        \
        int _c = tid + _k * 128;                                                    \
        int _t = _c / (BN * 8);                                                     \
        int _rm = _c % (BN * 8);                                                    \
        int _row = _rm >> 3, _co = _rm & 7;                                         \
        int _tap = _r * 3 + _t;                                                     \
        cp_async16(sb + (BO) + A_SZ + _t * B_TAP + _row * 144 + _co * 16,           \
                   (const char*)(wgt + (size_t)(_tap * OC + oc0 + _row) * IC        \
                                 + _icc * 64) + _co * 16, 16u);                     \
    }                                                                               \
} while (0)

#define COMPUTE(BO) do {                                                            \
    _Pragma("unroll")                                                               \
    for (int _t = 0; _t < 3; ++_t) {                                                \
        const uint32_t _abase = sb + (BO) + _t * 144;                               \
        const uint32_t _bbase = sb + (BO) + A_SZ + _t * B_TAP;                      \
        _Pragma("unroll")                                                           \
        for (int _ks = 0; _ks < 4; ++_ks) {                                         \
            uint32_t _ah[4][4], _bh[8][2];                                          \
            _Pragma("unroll")                                                       \
            for (int _mf = 0; _mf < 4; ++_mf)                                       \
                ldmx4(_ah[_mf], _abase                                              \
                      + (uint32_t)(wm * 64 + _mf * 16 + (lane & 15)) * 144          \
                      + _ks * 32 + ((lane >> 4) << 4));                             \
            _Pragma("unroll")                                                       \
            for (int _nf = 0; _nf < 8; ++_nf)                                       \
                ldmx2(_bh[_nf], _bbase                                              \
                      + (uint32_t)(wn * 64 + _nf * 8 + (lane & 7)) * 144            \
                      + _ks * 32 + (((lane >> 3) & 1) << 4));                       \
            _Pragma("unroll")                                                       \
            for (int _mf = 0; _mf < 4; ++_mf)                                       \
                _Pragma("unroll")                                                   \
                for (int _nf = 0; _nf < 8; ++_nf)                                   \
                    mma_fp16(acc[_mf][_nf], _ah[_mf], _bh[_nf]);                    \
        }                                                                           \
    }                                                                               \
} while (0)

    FILL(0, 0);
    CP_COMMIT();
    for (int s = 0; s < NSTAGE; ++s) {
        if (s + 1 < NSTAGE) {
            FILL(s + 1, ((s + 1) & 1) * SBUF);
            CP_COMMIT();
            CP_WAIT1();
        } else {
            CP_WAIT0();
        }
        __syncthreads();
        COMPUTE((s & 1) * SBUF);
        __syncthreads();
    }

#undef FILL
#undef COMPUTE

    // ---- epilogue
    float* outb = out + ((size_t)b * OC + oc0) * HW + (size_t)y * W + x0;
    const int rr0 = lane >> 2, cj = (lane & 3) * 2;

    if (MODE == 0) {
        #pragma unroll
        for (int mf = 0; mf < 4; ++mf)
            #pragma unroll
            for (int nf = 0; nf < 8; ++nf)
                #pragma unroll
                for (int q = 0; q < 4; ++q) {
                    int p   = wm * 64 + mf * 16 + rr0 + (q >> 1) * 8;
                    int ocl = wn * 64 + nf * 8 + cj + (q & 1);
                    outb[(size_t)ocl * HW + p] = acc[mf][nf][q];
                }
    } else {
        float ss[16], qq[16];
        #pragma unroll
        for (int i = 0; i < 16; ++i) { ss[i] = 0.f; qq[i] = 0.f; }
        #pragma unroll
        for (int nf = 0; nf < 8; ++nf)
            #pragma unroll
            for (int j = 0; j < 2; ++j) {
                int ocl = wn * 64 + nf * 8 + cj + j;
                float bv = __ldg(bias + oc0 + ocl);
                int idx = nf * 2 + j;
                #pragma unroll
                for (int mf = 0; mf < 4; ++mf)
                    #pragma unroll
                    for (int rr = 0; rr < 2; ++rr) {
                        float v = acc[mf][nf][rr * 2 + j] + bv;
                        int p = wm * 64 + mf * 16 + rr0 + rr * 8;
                        outb[(size_t)ocl * HW + p] = v;
                        ss[idx] += v;
                        qq[idx] += v * v;
                    }
            }
        #pragma unroll
        for (int i = 0; i < 16; ++i) {
            #pragma unroll
            for (int o = 4; o <= 16; o <<= 1) {
                ss[i] += __shfl_xor_sync(0xffffffffu, ss[i], o);
                qq[i] += __shfl_xor_sync(0xffffffffu, qq[i], o);
            }
        }
        if (lane < 4) {
            #pragma unroll
            for (int i = 0; i < 16; ++i) {
                int oc = oc0 + wn * 64 + (i >> 1) * 8 + lane * 2 + (i & 1);
                atomicAdd(&st_sum[oc], ss[i]);
                atomicAdd(&st_sq[oc], qq[i]);
            }
        }
    }
}

// ---------------- BN finalize -----------------------------------------------------
__global__ void bnfin_kernel(const float* __restrict__ sum, const float* __restrict__ sq,
                             const float* __restrict__ g, const float* __restrict__ bb,
                             float* __restrict__ scale, float* __restrict__ shift) {
    int c = threadIdx.x;
    float m = sum[c] / BN_N;
    float v = sq[c] / BN_N - m * m;
    float inv = rsqrtf(v + BN_EPS);
    float sc = g[c] * inv;
    scale[c] = sc;
    shift[c] = bb[c] - m * sc;
}

// ---------------- in-place BN + ReLU on output --------------------------------------
__global__ void final_bnrelu_kernel(float* __restrict__ out,
                                    const float* __restrict__ scale,
                                    const float* __restrict__ shift) {
    size_t idx = (size_t)blockIdx.x * blockDim.x + threadIdx.x;
    if (idx >= (size_t)BATCH * OUT_CH * HW) return;
    int c = (int)(idx >> 16) & (OUT_CH - 1);
    out[idx] = fmaxf(fmaf(out[idx], scale[c], shift[c]), 0.f);
}

// ---------------- launch -------------------------------------------------------------
extern "C" void kernel_launch(void* const* d_in, const int* in_sizes, int n_in,
                              void* d_out, int out_size) {
    const float* x1   = (const float*)d_in[0];
    const float* x2   = (const float*)d_in[1];
    const float* up_w = (const float*)d_in[2];
    const float* up_b = (const float*)d_in[3];
    const float* off_w= (const float*)d_in[4];
    const float* c1_w = (const float*)d_in[5];
    const float* c1_b = (const float*)d_in[6];
    const float* g1   = (const float*)d_in[7];
    const float* b1   = (const float*)d_in[8];
    const float* c2_w = (const float*)d_in[9];
    const float* c2_b = (const float*)d_in[10];
    const float* g2   = (const float*)d_in[11];
    const float* b2   = (const float*)d_in[12];
    float* out = (float*)d_out;

    float *up, *off, *pre1, *stats, *bn;
    __half *xc16, *xd16, *p116, *w16, *w116, *w216;
    cudaGetSymbolAddress((void**)&up,    g_up);
    cudaGetSymbolAddress((void**)&off,   g_off);
    cudaGetSymbolAddress((void**)&pre1,  g_pre1);
    cudaGetSymbolAddress((void**)&stats, g_stats);
    cudaGetSymbolAddress((void**)&bn,    g_bn);
    cudaGetSymbolAddress((void**)&xc16,  g_xc16);
    cudaGetSymbolAddress((void**)&xd16,  g_xd16);
    cudaGetSymbolAddress((void**)&p116,  g_p116);
    cudaGetSymbolAddress((void**)&w16,   g_w_off16);
    cudaGetSymbolAddress((void**)&w116,  g_w_c116);
    cudaGetSymbolAddress((void**)&w216,  g_w_c216);

    float* sum1 = stats;            float* sq1 = stats + 64;
    float* sum2 = stats + 128;      float* sq2 = stats + 192;
    float* sc1 = bn;                float* sh1 = bn + 64;
    float* sc2 = bn + 128;          float* sh2 = bn + 192;

    // smem sizes: off = 2*(130*144 + 3*128*144); conv = 2*(258*144 + 3*64*144)
    const int SMEM_OFF = 2 * (130 * 144 + 3 * 128 * 144);   // 148032
    const int SMEM_CV  = 2 * (258 * 144 + 3 * 64 * 144);    // 129600
    cudaFuncSetAttribute((const void*)conv_hmma_kernel<IN_CH, 0, 128, 128>,
                         cudaFuncAttributeMaxDynamicSharedMemorySize, SMEM_OFF);
    cudaFuncSetAttribute((const void*)conv_hmma_kernel<IN_CH, 1, 256, 64>,
                         cudaFuncAttributeMaxDynamicSharedMemorySize, SMEM_CV);
    cudaFuncSetAttribute((const void*)conv_hmma_kernel<OUT_CH, 1, 256, 64>,
                         cudaFuncAttributeMaxDynamicSharedMemorySize, SMEM_CV);

    // 1. pack offset weights (fp16)
    {
        int n0 = 9 * OFF_CH * IN_CH;
        pack_weights16_kernel<<<(n0 + 255) / 256, 256>>>(off_w, w16, OFF_CH, IN_CH);
    }
    // 2. conv-transpose upsample
    upcat2_kernel<<<dim3(64, 64, BATCH), 256>>>(x1, up_w, up_b);
    // 3. concat (x2 | up) -> NHWC fp16 plane
    nchw_to_fp16_kernel<<<dim3(HW / 32, IN_CH / 32, BATCH), dim3(32, 8)>>>(
        x2, up, xc16, IN_CH, C1, nullptr, nullptr);
    // 4. offset conv: (B,128) -> (B,256), block 128px x 128oc
    conv_hmma_kernel<IN_CH, 0, 128, 128>
        <<<dim3(512, OFF_CH / 128, BATCH), 128, SMEM_OFF>>>(
        xc16, w16, OFF_CH, nullptr, off, nullptr, nullptr);
    // 5-6. remaining packs + stats init
    {
        int n1 = 9 * OUT_CH * IN_CH;
        pack_weights16_kernel<<<(n1 + 255) / 256, 256>>>(c1_w, w116, OUT_CH, IN_CH);
        int n2 = 9 * OUT_CH * OUT_CH;
        pack_weights16_kernel<<<(n2 + 255) / 256, 256>>>(c2_w, w216, OUT_CH, OUT_CH);
    }
    init_stats_kernel<<<1, 256>>>();
    // 7. deformable gather -> NHWC fp16 plane
    gather_nhwc_kernel<<<dim3(HW / 32, IN_CH / 32, BATCH), dim3(32, 8)>>>(x2);
    // 8. conv1: (B,128) -> (B,64), block 256px x 64oc, bias + stats
    conv_hmma_kernel<IN_CH, 1, 256, 64><<<dim3(256, 1, BATCH), 128, SMEM_CV>>>(
        xd16, w116, OUT_CH, c1_b, pre1, sum1, sq1);
    bnfin_kernel<<<1, 64>>>(sum1, sq1, g1, b1, sc1, sh1);
    // 9. pre1 -> BN+ReLU -> NHWC fp16 plane
    nchw_to_fp16_kernel<<<dim3(HW / 32, OUT_CH / 32, BATCH), dim3(32, 8)>>>(
        pre1, pre1, p116, OUT_CH, OUT_CH, sc1, sh1);
    // 10. conv2: (B,64) -> (B,64), bias + stats
    conv_hmma_kernel<OUT_CH, 1, 256, 64><<<dim3(256, 1, BATCH), 128, SMEM_CV>>>(
        p116, w216, OUT_CH, c2_b, out, sum2, sq2);
    bnfin_kernel<<<1, 64>>>(sum2, sq2, g2, b2, sc2, sh2);
    // 11. final BN + ReLU
    {
        size_t n = (size_t)BATCH * OUT_CH * HW;
        final_bnrelu_kernel<<<(unsigned)((n + 255) / 256), 256>>>(out, sc2, sh2);
    }
}

// round 13
// speedup vs baseline: 1.0612x; 1.0612x over previous
#include <cuda_runtime.h>
#include <cuda_bf16.h>
#include <cuda_fp16.h>
#include <math.h>
#include <stdint.h>

// Problem constants
#define BATCH   2
#define C1      64
#define IN_CH   128
#define OFF_CH  256
#define OUT_CH  64
#define H1      128
#define W1      128
#define H       256
#define W       256
#define HW      (H*W)
#define BN_EPS  1e-5f
#define BN_N    ((float)(BATCH*H*W))

// ---------------- scratch ------------------------------------------------------
__device__ float g_up  [(size_t)BATCH * C1 * HW];
__device__ float g_pre1[(size_t)BATCH * OUT_CH * HW];
__device__ float g_stats[4 * OUT_CH];
__device__ float g_bn   [4 * OUT_CH];

// offsets stored fp16 (same flat layout as NCHW conv output)
__device__ __half g_off16[(size_t)BATCH * OFF_CH * HW];

// NHWC fp16 planes ([b][pix][ic], ic contiguous)
__device__ __half g_xc16[(size_t)BATCH * HW * IN_CH];
__device__ __half g_xd16[(size_t)BATCH * HW * IN_CH];
__device__ __half g_p116[(size_t)BATCH * HW * OUT_CH];

// packed fp16 weights [tap][oc][ic]
__device__ __half g_w_off16[9 * OFF_CH * IN_CH];
__device__ __half g_w_c116 [9 * OUT_CH * IN_CH];
__device__ __half g_w_c216 [9 * OUT_CH * OUT_CH];

// ---------------- PTX helpers ----------------------------------------------------
__device__ __forceinline__ uint32_t smem_u32(const void* p) {
    uint32_t a;
    asm("{ .reg .u64 t; cvta.to.shared.u64 t, %1; cvt.u32.u64 %0, t; }"
        : "=r"(a) : "l"(p));
    return a;
}
__device__ __forceinline__ void ldmx4(uint32_t* r, uint32_t a) {
    asm volatile("ldmatrix.sync.aligned.m8n8.x4.shared.b16 {%0,%1,%2,%3}, [%4];"
        : "=r"(r[0]), "=r"(r[1]), "=r"(r[2]), "=r"(r[3]) : "r"(a));
}
__device__ __forceinline__ void ldmx2(uint32_t* r, uint32_t a) {
    asm volatile("ldmatrix.sync.aligned.m8n8.x2.shared.b16 {%0,%1}, [%2];"
        : "=r"(r[0]), "=r"(r[1]) : "r"(a));
}
__device__ __forceinline__ void mma_fp16(float* d, const uint32_t* A, const uint32_t* B) {
    asm volatile(
        "mma.sync.aligned.m16n8k16.row.col.f32.f16.f16.f32 "
        "{%0,%1,%2,%3}, {%4,%5,%6,%7}, {%8,%9}, {%0,%1,%2,%3};"
        : "+f"(d[0]), "+f"(d[1]), "+f"(d[2]), "+f"(d[3])
        : "r"(A[0]), "r"(A[1]), "r"(A[2]), "r"(A[3]), "r"(B[0]), "r"(B[1]));
}
__device__ __forceinline__ void cp_async16(uint32_t dst, const void* src, uint32_t srcsize) {
    asm volatile("cp.async.cg.shared.global [%0], [%1], 16, %2;"
                 :: "r"(dst), "l"(src), "r"(srcsize) : "memory");
}
#define CP_COMMIT() asm volatile("cp.async.commit_group;" ::: "memory")
#define CP_WAIT1()  asm volatile("cp.async.wait_group 1;" ::: "memory")
#define CP_WAIT0()  asm volatile("cp.async.wait_group 0;" ::: "memory")

// ---------------- small kernels ----------------------------------------------------
__global__ void init_stats_kernel() { g_stats[threadIdx.x] = 0.f; }

// (OC,IC,3,3) fp32 -> [tap][oc][ic] fp16
__global__ void pack_weights16_kernel(const float* __restrict__ w,
                                      __half* __restrict__ dst,
                                      int OC, int IC) {
    int idx = blockIdx.x * blockDim.x + threadIdx.x;
    int total = 9 * OC * IC;
    if (idx >= total) return;
    int ic  = idx % IC;
    int rem = idx / IC;
    int oc  = rem % OC;
    int tap = rem / OC;
    dst[idx] = __float2half_rn(w[((size_t)oc * IC + ic) * 9 + tap]);
}

// ConvTranspose2d(2,2,s=2): thread computes 2x2 px x 4 o-channels (16 outputs)
__global__ void upcat4_kernel(const float* __restrict__ x1,
                              const float* __restrict__ up_w,
                              const float* __restrict__ up_b) {
    __shared__ float w4[64][4][4];   // [ic][oc_l][k]
    int tid = threadIdx.x;
    int o0 = blockIdx.y * 4, b = blockIdx.z;
    for (int l = tid; l < 64 * 4 * 4; l += 256) {
        int k = l & 3, ol = (l >> 2) & 3, i = l >> 4;
        w4[i][ol][k] = up_w[((size_t)i * 64 + o0 + ol) * 4 + k];
    }
    __syncthreads();
    int pix = blockIdx.x * 256 + tid;
    int ys = pix >> 7, xs = pix & 127;
    float acc[4][4];
    #pragma unroll
    for (int ol = 0; ol < 4; ++ol) {
        float bv = up_b[o0 + ol];
        #pragma unroll
        for (int k = 0; k < 4; ++k) acc[ol][k] = bv;
    }
    const float* xp = x1 + (size_t)b * C1 * H1 * W1 + pix;
    #pragma unroll 4
    for (int i = 0; i < 64; ++i) {
        float v = __ldg(xp + (size_t)i * (H1 * W1));
        #pragma unroll
        for (int ol = 0; ol < 4; ++ol) {
            acc[ol][0] = fmaf(v, w4[i][ol][0], acc[ol][0]);
            acc[ol][1] = fmaf(v, w4[i][ol][1], acc[ol][1]);
            acc[ol][2] = fmaf(v, w4[i][ol][2], acc[ol][2]);
            acc[ol][3] = fmaf(v, w4[i][ol][3], acc[ol][3]);
        }
    }
    #pragma unroll
    for (int ol = 0; ol < 4; ++ol) {
        float* dst = g_up + ((size_t)(b * C1 + o0 + ol) * H + 2 * ys) * W + 2 * xs;
        *(float2*)dst = make_float2(acc[ol][0], acc[ol][1]);
        *(float2*)(dst + W) = make_float2(acc[ol][2], acc[ol][3]);
    }
}

// NCHW fp32 (two srcs, split at S) -> NHWC fp16 (optional BN+ReLU). block (32,8).
__global__ void nchw_to_fp16_kernel(const float* __restrict__ src_lo,
                                    const float* __restrict__ src_hi,
                                    __half* __restrict__ dst, int C, int S,
                                    const float* __restrict__ sc,
                                    const float* __restrict__ sh) {
    __shared__ float t[32][33];
    int tx = threadIdx.x, ty = threadIdx.y;
    int pix0 = blockIdx.x * 32, cg = blockIdx.y * 32, b = blockIdx.z;
    #pragma unroll
    for (int i = 0; i < 4; ++i) {
        int c = cg + ty + i * 8;
        const float* sp = (c < S) ? src_lo + ((size_t)b * S + c) * HW
                                  : src_hi + ((size_t)b * (C - S) + c - S) * HW;
        float v = sp[pix0 + tx];
        if (sc) v = fmaxf(fmaf(v, __ldg(sc + c), __ldg(sh + c)), 0.f);
        t[ty + i * 8][tx] = v;
    }
    __syncthreads();
    #pragma unroll
    for (int i = 0; i < 4; ++i) {
        int pxl = ty + i * 8;
        size_t o = ((size_t)b * HW + pix0 + pxl) * C + cg + tx;
        dst[o] = __float2half_rn(t[tx][pxl]);
    }
}

// deformable gather (fp16 offsets) fused with NHWC fp16 transpose. block (32,8).
__global__ void gather_nhwc_kernel(const float* __restrict__ x2) {
    __shared__ float t[32][33];
    int tx = threadIdx.x, ty = threadIdx.y;
    int pix0 = blockIdx.x * 32, cg = blockIdx.y * 32, b = blockIdx.z;
    int pix = pix0 + tx;
    int x = pix & (W - 1), y = pix >> 8;
    const __half* ob = g_off16 + (size_t)b * OFF_CH * HW;
    #pragma unroll
    for (int i = 0; i < 4; ++i) {
        int c = cg + ty + i * 8;
        size_t flat = 2 * ((size_t)c * HW + pix);
        __half2 o2 = *reinterpret_cast<const __half2*>(ob + flat);
        float oy = __half2float(__low2half(o2));
        float ox = __half2float(__high2half(o2));
        float cy = fminf(fmaxf(oy + (float)y, 0.f), (float)(H - 1));
        float cx = fminf(fmaxf(ox + (float)x, 0.f), (float)(W - 1));
        float y0f = floorf(cy), x0f = floorf(cx);
        int y0 = (int)y0f, y1 = (int)ceilf(cy);
        int xx0 = (int)x0f, xx1 = (int)ceilf(cx);
        const float* xp = (c < C1) ? x2 + ((size_t)b * C1 + c) * HW
                                   : g_up + ((size_t)b * C1 + c - C1) * HW;
        float v00 = xp[y0 * W + xx0];
        float v10 = xp[y1 * W + xx0];
        float v01 = xp[y0 * W + xx1];
        float v11 = xp[y1 * W + xx1];
        float wy = cy - y0f, wx = cx - x0f;
        float vt = fmaf(v10 - v00, wy, v00);
        float vb = fmaf(v11 - v01, wy, v01);
        t[ty + i * 8][tx] = fmaf(vb - vt, wx, vt);
    }
    __syncthreads();
    #pragma unroll
    for (int i = 0; i < 4; ++i) {
        int pxl = ty + i * 8;
        size_t o = ((size_t)b * HW + pix0 + pxl) * IN_CH + cg + tx;
        g_xd16[o] = __float2half_rn(t[tx][pxl]);
    }
}

// ---------------- fp16 HMMA conv (R11 config), A-row reuse across dx taps ----------
// Block: M=128 px x N=64 oc, 4 warps (2m x 2n), warp tile 64x32.
// Stage = (icc, row dy). MODE 0: plain, fp16 output. MODE 1: fp32 out, +bias,+stats.
template <int IC, int MODE>
__global__ __launch_bounds__(128, 2)
void conv_hmma_kernel(const __half* __restrict__ xin,
                      const __half* __restrict__ wgt,
                      int OC,
                      const float* __restrict__ bias, void* __restrict__ outv,
                      float* __restrict__ st_sum, float* __restrict__ st_sq) {
    extern __shared__ __align__(128) char smem[];
    constexpr int NSTAGE = (IC / 64) * 3;
    constexpr int A_SZ  = 130 * 144;               // 18720
    constexpr int B_TAP = 64 * 144;                // 9216
    constexpr int SBUF  = A_SZ + 3 * B_TAP;        // 46368

    const int tid = threadIdx.x, lane = tid & 31, wid = tid >> 5;
    const int wm = wid & 1, wn = wid >> 1;
    const int y  = blockIdx.x >> 1;
    const int x0 = (blockIdx.x & 1) * 128;
    const int b  = blockIdx.z;
    const int oc0 = blockIdx.y * 64;
    const uint32_t sb = smem_u32(smem);
    const __half* xb = xin + (size_t)b * HW * IC;

    float acc[4][4][4];
    #pragma unroll
    for (int mf = 0; mf < 4; ++mf)
        #pragma unroll
        for (int nf = 0; nf < 4; ++nf)
            #pragma unroll
            for (int q = 0; q < 4; ++q) acc[mf][nf][q] = 0.f;

#define FILL(S, BO) do {                                                            \
    const int _s = (S);                                                             \
    const int _icc = (IC == 128) ? (_s / 3) : 0;                                    \
    const int _r   = (IC == 128) ? (_s % 3) : _s;                                   \
    const int _ys = y + _r - 1;                                                     \
    const bool _yok = (_ys >= 0) && (_ys < H);                                      \
    _Pragma("unroll")                                                               \
    for (int _k = 0; _k < 9; ++_k) {                                                \
        int _c = tid + _k * 128;                                                    \
        if (_c < 1040) {                                                            \
            int _px = _c >> 3, _co = _c & 7;                                        \
            int _xs = x0 + _px - 1;                                                 \
            bool _ok = _yok && (_xs >= 0) && (_xs < W);                             \
            size_t _po = _ok ? ((size_t)_ys * W + _xs) * IC : 0;                    \
            cp_async16(sb + (BO) + _px * 144 + _co * 16,                            \
                       (const char*)(xb + _po) + _icc * 128 + _co * 16,             \
                       _ok ? 16u : 0u);                                             \
        }                                                                           \
    }                                                                               \
    _Pragma("unroll")                                                               \
    for (int _k = 0; _k < 12; ++_k) {                                               \
        int _c = tid + _k * 128;                                                    \
        int _t = _c >> 9;                                                           \
        int _rm = _c & 511;                                                         \
        int _row = _rm >> 3, _co = _rm & 7;                                         \
        int _tap = _r * 3 + _t;                                                     \
        cp_async16(sb + (BO) + A_SZ + _t * B_TAP + _row * 144 + _co * 16,           \
                   (const char*)(wgt + (size_t)(_tap * OC + oc0 + _row) * IC        \
                                 + _icc * 64) + _co * 16, 16u);                     \
    }                                                                               \
} while (0)

#define COMPUTE(BO) do {                                                            \
    _Pragma("unroll")                                                               \
    for (int _t = 0; _t < 3; ++_t) {                                                \
        const uint32_t _abase = sb + (BO) + _t * 144;                               \
        const uint32_t _bbase = sb + (BO) + A_SZ + _t * B_TAP;                      \
        _Pragma("unroll")                                                           \
        for (int _ks = 0; _ks < 4; ++_ks) {                                         \
            uint32_t _ah[4][4], _bh[4][2];                                          \
            _Pragma("unroll")                                                       \
            for (int _mf = 0; _mf < 4; ++_mf)                                       \
                ldmx4(_ah[_mf], _abase                                              \
                      + (uint32_t)(wm * 64 + _mf * 16 + (lane & 15)) * 144          \
                      + _ks * 32 + ((lane >> 4) << 4));                             \
            _Pragma("unroll")                                                       \
            for (int _nf = 0; _nf < 4; ++_nf)                                       \
                ldmx2(_bh[_nf], _bbase                                              \
                      + (uint32_t)(wn * 32 + _nf * 8 + (lane & 7)) * 144            \
                      + _ks * 32 + (((lane >> 3) & 1) << 4));                       \
            _Pragma("unroll")                                                       \
            for (int _mf = 0; _mf < 4; ++_mf)                                       \
                _Pragma("unroll")                                                   \
                for (int _nf = 0; _nf < 4; ++_nf)                                   \
                    mma_fp16(acc[_mf][_nf], _ah[_mf], _bh[_nf]);                    \
        }                                                                           \
    }                                                                               \
} while (0)

    FILL(0, 0);
    CP_COMMIT();
    for (int s = 0; s < NSTAGE; ++s) {
        if (s + 1 < NSTAGE) {
            FILL(s + 1, ((s + 1) & 1) * SBUF);
            CP_COMMIT();
            CP_WAIT1();
        } else {
            CP_WAIT0();
        }
        __syncthreads();
        COMPUTE((s & 1) * SBUF);
        __syncthreads();
    }

#undef FILL
#undef COMPUTE

    // ---- epilogue
    const int rr0 = lane >> 2, cj = (lane & 3) * 2;

    if (MODE == 0) {
        // fp16 output (offsets)
        __half* outb = (__half*)outv + ((size_t)b * OC + oc0) * HW
                       + (size_t)y * W + x0;
        #pragma unroll
        for (int mf = 0; mf < 4; ++mf)
            #pragma unroll
            for (int nf = 0; nf < 4; ++nf)
                #pragma unroll
                for (int q = 0; q < 4; ++q) {
                    int p   = wm * 64 + mf * 16 + rr0 + (q >> 1) * 8;
                    int ocl = wn * 32 + nf * 8 + cj + (q & 1);
                    outb[(size_t)ocl * HW + p] = __float2half_rn(acc[mf][nf][q]);
                }
    } else {
        float* outb = (float*)outv + ((size_t)b * OC + oc0) * HW
                      + (size_t)y * W + x0;
        float ss[8], qq[8];
        #pragma unroll
        for (int i = 0; i < 8; ++i) { ss[i] = 0.f; qq[i] = 0.f; }
        #pragma unroll
        for (int nf = 0; nf < 4; ++nf)
            #pragma unroll
            for (int j = 0; j < 2; ++j) {
                int ocl = wn * 32 + nf * 8 + cj + j;
                float bv = __ldg(bias + oc0 + ocl);
                int idx = nf * 2 + j;
                #pragma unroll
                for (int mf = 0; mf < 4; ++mf)
                    #pragma unroll
                    for (int rr = 0; rr < 2; ++rr) {
                        float v = acc[mf][nf][rr * 2 + j] + bv;
                        int p = wm * 64 + mf * 16 + rr0 + rr * 8;
                        outb[(size_t)ocl * HW + p] = v;
                        ss[idx] += v;
                        qq[idx] += v * v;
                    }
            }
        #pragma unroll
        for (int i = 0; i < 8; ++i) {
            #pragma unroll
            for (int o = 4; o <= 16; o <<= 1) {
                ss[i] += __shfl_xor_sync(0xffffffffu, ss[i], o);
                qq[i] += __shfl_xor_sync(0xffffffffu, qq[i], o);
            }
        }
        if (lane < 4) {
            #pragma unroll
            for (int i = 0; i < 8; ++i) {
                int oc = oc0 + wn * 32 + (i >> 1) * 8 + lane * 2 + (i & 1);
                atomicAdd(&st_sum[oc], ss[i]);
                atomicAdd(&st_sq[oc], qq[i]);
            }
        }
    }
}

// ---------------- BN finalize -----------------------------------------------------
__global__ void bnfin_kernel(const float* __restrict__ sum, const float* __restrict__ sq,
                             const float* __restrict__ g, const float* __restrict__ bb,
                             float* __restrict__ scale, float* __restrict__ shift) {
    int c = threadIdx.x;
    float m = sum[c] / BN_N;
    float v = sq[c] / BN_N - m * m;
    float inv = rsqrtf(v + BN_EPS);
    float sc = g[c] * inv;
    scale[c] = sc;
    shift[c] = bb[c] - m * sc;
}

// ---------------- in-place BN + ReLU on output --------------------------------------
__global__ void final_bnrelu_kernel(float* __restrict__ out,
                                    const float* __restrict__ scale,
                                    const float* __restrict__ shift) {
    size_t idx = (size_t)blockIdx.x * blockDim.x + threadIdx.x;
    if (idx >= (size_t)BATCH * OUT_CH * HW) return;
    int c = (int)(idx >> 16) & (OUT_CH - 1);
    out[idx] = fmaxf(fmaf(out[idx], scale[c], shift[c]), 0.f);
}

// ---------------- launch -------------------------------------------------------------
extern "C" void kernel_launch(void* const* d_in, const int* in_sizes, int n_in,
                              void* d_out, int out_size) {
    const float* x1   = (const float*)d_in[0];
    const float* x2   = (const float*)d_in[1];
    const float* up_w = (const float*)d_in[2];
    const float* up_b = (const float*)d_in[3];
    const float* off_w= (const float*)d_in[4];
    const float* c1_w = (const float*)d_in[5];
    const float* c1_b = (const float*)d_in[6];
    const float* g1   = (const float*)d_in[7];
    const float* b1   = (const float*)d_in[8];
    const float* c2_w = (const float*)d_in[9];
    const float* c2_b = (const float*)d_in[10];
    const float* g2   = (const float*)d_in[11];
    const float* b2   = (const float*)d_in[12];
    float* out = (float*)d_out;

    float *up, *pre1, *stats, *bn;
    __half *off16, *xc16, *xd16, *p116, *w16, *w116, *w216;
    cudaGetSymbolAddress((void**)&up,    g_up);
    cudaGetSymbolAddress((void**)&pre1,  g_pre1);
    cudaGetSymbolAddress((void**)&stats, g_stats);
    cudaGetSymbolAddress((void**)&bn,    g_bn);
    cudaGetSymbolAddress((void**)&off16, g_off16);
    cudaGetSymbolAddress((void**)&xc16,  g_xc16);
    cudaGetSymbolAddress((void**)&xd16,  g_xd16);
    cudaGetSymbolAddress((void**)&p116,  g_p116);
    cudaGetSymbolAddress((void**)&w16,   g_w_off16);
    cudaGetSymbolAddress((void**)&w116,  g_w_c116);
    cudaGetSymbolAddress((void**)&w216,  g_w_c216);

    float* sum1 = stats;            float* sq1 = stats + 64;
    float* sum2 = stats + 128;      float* sq2 = stats + 192;
    float* sc1 = bn;                float* sh1 = bn + 64;
    float* sc2 = bn + 128;          float* sh2 = bn + 192;

    const int SMEM = 2 * 46368;   // 92736
    cudaFuncSetAttribute(conv_hmma_kernel<IN_CH, 0>,
                         cudaFuncAttributeMaxDynamicSharedMemorySize, SMEM);
    cudaFuncSetAttribute(conv_hmma_kernel<IN_CH, 1>,
                         cudaFuncAttributeMaxDynamicSharedMemorySize, SMEM);
    cudaFuncSetAttribute(conv_hmma_kernel<OUT_CH, 1>,
                         cudaFuncAttributeMaxDynamicSharedMemorySize, SMEM);

    // 1. pack offset weights (fp16)
    {
        int n0 = 9 * OFF_CH * IN_CH;
        pack_weights16_kernel<<<(n0 + 255) / 256, 256>>>(off_w, w16, OFF_CH, IN_CH);
    }
    // 2. conv-transpose upsample (4 oc per thread)
    upcat4_kernel<<<dim3(64, 16, BATCH), 256>>>(x1, up_w, up_b);
    // 3. concat (x2 | up) -> NHWC fp16 plane
    nchw_to_fp16_kernel<<<dim3(HW / 32, IN_CH / 32, BATCH), dim3(32, 8)>>>(
        x2, up, xc16, IN_CH, C1, nullptr, nullptr);
    // 4. offset conv: (B,128) -> (B,256), fp16 offsets out
    conv_hmma_kernel<IN_CH, 0><<<dim3(512, OFF_CH / 64, BATCH), 128, SMEM>>>(
        xc16, w16, OFF_CH, nullptr, off16, nullptr, nullptr);
    // 5-6. remaining packs + stats init
    {
        int n1 = 9 * OUT_CH * IN_CH;
        pack_weights16_kernel<<<(n1 + 255) / 256, 256>>>(c1_w, w116, OUT_CH, IN_CH);
        int n2 = 9 * OUT_CH * OUT_CH;
        pack_weights16_kernel<<<(n2 + 255) / 256, 256>>>(c2_w, w216, OUT_CH, OUT_CH);
    }
    init_stats_kernel<<<1, 256>>>();
    // 7. deformable gather (fp16 offsets) -> NHWC fp16 plane
    gather_nhwc_kernel<<<dim3(HW / 32, IN_CH / 32, BATCH), dim3(32, 8)>>>(x2);
    // 8. conv1: (B,128) -> (B,64), bias + stats
    conv_hmma_kernel<IN_CH, 1><<<dim3(512, 1, BATCH), 128, SMEM>>>(
        xd16, w116, OUT_CH, c1_b, pre1, sum1, sq1);
    bnfin_kernel<<<1, 64>>>(sum1, sq1, g1, b1, sc1, sh1);
    // 9. pre1 -> BN+ReLU -> NHWC fp16 plane
    nchw_to_fp16_kernel<<<dim3(HW / 32, OUT_CH / 32, BATCH), dim3(32, 8)>>>(
        pre1, pre1, p116, OUT_CH, OUT_CH, sc1, sh1);
    // 10. conv2: (B,64) -> (B,64), bias + stats
    conv_hmma_kernel<OUT_CH, 1><<<dim3(512, 1, BATCH), 128, SMEM>>>(
        p116, w216, OUT_CH, c2_b, out, sum2, sq2);
    bnfin_kernel<<<1, 64>>>(sum2, sq2, g2, b2, sc2, sh2);
    // 11. final BN + ReLU
    {
        size_t n = (size_t)BATCH * OUT_CH * HW;
        final_bnrelu_kernel<<<(unsigned)((n + 255) / 256), 256>>>(out, sc2, sh2);
    }
}